// round 16
// baseline (speedup 1.0000x reference)
#include <cuda_runtime.h>
#include <cuda_bf16.h>
#include <math.h>

// Problem dims (fixed by the reference)
#define T_STEPS 512
#define BATCH   256
#define DIM     1024
#define HID     1024
#define OUTD    5

// Recurrence (R10 shell): 128 CTAs = 8 m-groups(32) x 16 n-tiles(64)
#define GRID_P  128
#define MT      32
#define NT      64
#define RSTR    68            // padded fp32 row stride in reduction buffer
#define RKQ     (32 * RSTR)   // per-k-quarter stride (2176 words)

// Scratch
__device__ float          g_E[(size_t)T_STEPS * BATCH * HID];     // fp32 input proj
__device__ __nv_bfloat16  g_hbf[2][(size_t)BATCH * HID];          // bf16 h transport
__device__ float          g_hfinal[(size_t)BATCH * HID];          // fp32 final h
__device__ unsigned       g_grp2[8][2][32];                       // per (group, k-half) ctrs

// ---------------------------------------------------------------------------
__device__ __forceinline__ void mma_bf16(float d[4],
                                         unsigned a0, unsigned a1,
                                         unsigned a2, unsigned a3,
                                         unsigned b0, unsigned b1)
{
    asm volatile(
        "mma.sync.aligned.m16n8k16.row.col.f32.bf16.bf16.f32 "
        "{%0,%1,%2,%3}, {%4,%5,%6,%7}, {%8,%9}, {%0,%1,%2,%3};"
        : "+f"(d[0]), "+f"(d[1]), "+f"(d[2]), "+f"(d[3])
        : "r"(a0), "r"(a1), "r"(a2), "r"(a3), "r"(b0), "r"(b1));
}

__device__ __forceinline__ float sigmoidf_fast(float x)
{
    return 1.0f / (1.0f + __expf(-x));
}

// ---------------------------------------------------------------------------
// E = x @ W_in^T + b_in, single-pass bf16 tensor-core GEMM (validated R7-R14).
// ---------------------------------------------------------------------------
__global__ void __launch_bounds__(256, 2)
egemm_bf16(const float* __restrict__ X,     // [131072, 1024]
           const float* __restrict__ Wg,    // [1024, 1024]
           const float* __restrict__ bias,  // [1024]
           float* __restrict__ E)
{
    extern __shared__ unsigned es[];
    unsigned* Ah = es;              // 8192 words (32KB)
    unsigned* Bh = es + 8192;       // 4096 words (16KB)

    const int tid  = threadIdx.x;
    const int lane = tid & 31;
    const int w    = tid >> 5;
    const int qid  = lane >> 2;
    const int c    = lane & 3;
    const int g    = w >> 1;
    const int subm = (w & 1) * 16;

    const int n0 = blockIdx.x * 64;
    const int m0 = blockIdx.y * 128;

    const int srow = tid >> 3;
    const int ssl  = tid & 7;
    const int sx   = ssl & 3;

    float acc[4][2][4];
    #pragma unroll
    for (int a = 0; a < 4; a++)
        #pragma unroll
        for (int b = 0; b < 2; b++)
            #pragma unroll
            for (int d = 0; d < 4; d++) acc[a][b][d] = 0.0f;

    for (int ch = 0; ch < 8; ch++) {
        __syncthreads();
        const float* xbase = X + (size_t)(m0 + srow) * 1024 + ch * 128 + ssl * 16;
        #pragma unroll
        for (int jj = 0; jj < 4; jj++) {
            const float4* p = (const float4*)(xbase + (size_t)jj * 32 * 1024);
            float4 f0 = p[0], f1 = p[1], f2 = p[2], f3 = p[3];
            unsigned h[8];
            {
                __nv_bfloat162 b0 = __float22bfloat162_rn(make_float2(f0.x, f0.y));
                __nv_bfloat162 b1 = __float22bfloat162_rn(make_float2(f0.z, f0.w));
                __nv_bfloat162 b2 = __float22bfloat162_rn(make_float2(f1.x, f1.y));
                __nv_bfloat162 b3 = __float22bfloat162_rn(make_float2(f1.z, f1.w));
                __nv_bfloat162 b4 = __float22bfloat162_rn(make_float2(f2.x, f2.y));
                __nv_bfloat162 b5 = __float22bfloat162_rn(make_float2(f2.z, f2.w));
                __nv_bfloat162 b6 = __float22bfloat162_rn(make_float2(f3.x, f3.y));
                __nv_bfloat162 b7 = __float22bfloat162_rn(make_float2(f3.z, f3.w));
                h[0] = *(unsigned*)&b0; h[1] = *(unsigned*)&b1;
                h[2] = *(unsigned*)&b2; h[3] = *(unsigned*)&b3;
                h[4] = *(unsigned*)&b4; h[5] = *(unsigned*)&b5;
                h[6] = *(unsigned*)&b6; h[7] = *(unsigned*)&b7;
            }
            uint2* dh = (uint2*)&Ah[jj * 2048 + ssl * 256 + srow * 8];
            dh[0 ^ sx] = make_uint2(h[0], h[4]);
            dh[1 ^ sx] = make_uint2(h[1], h[5]);
            dh[2 ^ sx] = make_uint2(h[2], h[6]);
            dh[3 ^ sx] = make_uint2(h[3], h[7]);
        }
        #pragma unroll
        for (int jj = 0; jj < 2; jj++) {
            int nrow = srow + jj * 32;
            const float4* p = (const float4*)(Wg + (size_t)(n0 + nrow) * 1024
                                              + ch * 128 + ssl * 16);
            float4 f0 = p[0], f1 = p[1], f2 = p[2], f3 = p[3];
            unsigned h[8];
            {
                __nv_bfloat162 b0 = __float22bfloat162_rn(make_float2(f0.x, f0.y));
                __nv_bfloat162 b1 = __float22bfloat162_rn(make_float2(f0.z, f0.w));
                __nv_bfloat162 b2 = __float22bfloat162_rn(make_float2(f1.x, f1.y));
                __nv_bfloat162 b3 = __float22bfloat162_rn(make_float2(f1.z, f1.w));
                __nv_bfloat162 b4 = __float22bfloat162_rn(make_float2(f2.x, f2.y));
                __nv_bfloat162 b5 = __float22bfloat162_rn(make_float2(f2.z, f2.w));
                __nv_bfloat162 b6 = __float22bfloat162_rn(make_float2(f3.x, f3.y));
                __nv_bfloat162 b7 = __float22bfloat162_rn(make_float2(f3.z, f3.w));
                h[0] = *(unsigned*)&b0; h[1] = *(unsigned*)&b1;
                h[2] = *(unsigned*)&b2; h[3] = *(unsigned*)&b3;
                h[4] = *(unsigned*)&b4; h[5] = *(unsigned*)&b5;
                h[6] = *(unsigned*)&b6; h[7] = *(unsigned*)&b7;
            }
            uint2* dh = (uint2*)&Bh[ssl * 512 + nrow * 8];
            dh[0 ^ sx] = make_uint2(h[0], h[4]);
            dh[1 ^ sx] = make_uint2(h[1], h[5]);
            dh[2 ^ sx] = make_uint2(h[2], h[6]);
            dh[3 ^ sx] = make_uint2(h[3], h[7]);
        }
        __syncthreads();

        #pragma unroll
        for (int sl = 0; sl < 8; sl++) {
            int axw = g * 2048 + sl * 256 + (subm + qid) * 8 + 2 * (c ^ (sl & 3));
            uint2 ah0 = *(const uint2*)&Ah[axw];
            uint2 ah1 = *(const uint2*)&Ah[axw + 64];
            #pragma unroll
            for (int ng = 0; ng < 4; ng++) {
                int bxw = sl * 512 + ng * 128 + qid * 8 + 2 * (c ^ (sl & 3));
                uint2 bh0 = *(const uint2*)&Bh[bxw];
                uint2 bh1 = *(const uint2*)&Bh[bxw + 64];
                mma_bf16(acc[ng][0], ah0.x, ah1.x, ah0.y, ah1.y, bh0.x, bh0.y);
                mma_bf16(acc[ng][1], ah0.x, ah1.x, ah0.y, ah1.y, bh1.x, bh1.y);
            }
        }
    }

    const int mrow = m0 + w * 16 + qid;
    #pragma unroll
    for (int ng = 0; ng < 4; ng++) {
        #pragma unroll
        for (int hh = 0; hh < 2; hh++) {
            int col = n0 + ng * 16 + hh * 8 + 2 * c;
            float2 b2 = *(const float2*)(bias + col);
            float2 o0, o1;
            o0.x = acc[ng][hh][0] + b2.x; o0.y = acc[ng][hh][1] + b2.y;
            o1.x = acc[ng][hh][2] + b2.x; o1.y = acc[ng][hh][3] + b2.y;
            *(float2*)&E[(size_t)mrow * 1024 + col]       = o0;
            *(float2*)&E[(size_t)(mrow + 8) * 1024 + col] = o1;
        }
    }
}

// ---------------------------------------------------------------------------
__global__ void h0_to_bf16(const float* __restrict__ h0)
{
    int i = blockIdx.x * 256 + threadIdx.x;
    g_hbf[1][i] = __float2bfloat16(h0[i]);
}

// Dummy launch: shifts ncu's fixed capture slot onto rnn_persistent.
__global__ void ncu_shift_dummy() {}

// ---------------------------------------------------------------------------
// Persistent recurrence, R15: R10 kernel with the monolithic group barrier
// split into TWO k-half barriers, each owned by a disjoint warp quad.
// Warps 0-3 (kq 0,1) consume k 0..511   <- producers 0-7   (counter [grp][0])
// Warps 4-7 (kq 2,3) consume k 512..1023 <- producers 8-15 (counter [grp][1])
// Each half: poll -> bar.sync(1+half,128) -> bulk LDG (16 int4/thr) ->
// stage -> bar -> MMA 16 slices -> bar (WAR) -> Red write into its OWN As
// half (base = half*8192 + (kq&1)*RKQ). Full __syncthreads only before the
// epilogue and the release. One half's LDG/stage overlaps the other's MMA.
// ---------------------------------------------------------------------------
__global__ void __launch_bounds__(256, 1)
rnn_persistent(const float* __restrict__ W_h,
               const float* __restrict__ b_h)
{
    extern __shared__ unsigned smw[];
    unsigned* Ws = smw;              // 32768 words (128KB)
    unsigned* As = smw + 32768;      // 16384 words (64KB)
    float*    Red = (float*)As;      // reduction buffer (reuses As)

    const int tid  = threadIdx.x;
    const int lane = tid & 31;
    const int w    = tid >> 5;
    const int qid  = lane >> 2;
    const int c    = lane & 3;
    const int mw   = (w >> 2) * 16;  // epilogue coords (R10 mapping)
    const int nw   = (w & 3) * 16;
    const int nh   = w & 1;          // MMA role: n-half (32 cols)
    const int kq   = w >> 1;         // MMA role: k-quarter (256 k)
    const int half = w >> 2;         // k-half this warp belongs to (== kq>>1)
    const int cta  = blockIdx.x;
    const int grp  = cta >> 4;
    const int myp  = cta & 15;       // producer index within group
    const int m0   = grp * MT;
    const int n0   = myp * NT;

    // ---- fill Ws (once): fp32 -> bf16x2, fragment-shuffled (R8 layout) ----
    for (int i = tid; i < NT * 512; i += 256) {
        int n  = i >> 9;
        int kp = i & 511;
        int k  = kp * 2;
        int s  = k >> 4;
        int p  = (k & 15) >> 1;
        float2 wv = *(const float2*)(W_h + (size_t)(n0 + n) * HID + k);
        __nv_bfloat162 bb = __float22bfloat162_rn(wv);
        Ws[s * 512 + n * 8 + (p & 3) * 2 + (p >> 2)] = *(unsigned*)&bb;
    }
    const float2 bh0 = *(const float2*)(b_h + n0 + nw + 2 * c);
    const float2 bh1 = *(const float2*)(b_h + n0 + nw + 8 + 2 * c);
    __syncthreads();

    // half-local staging coords: 128 threads cover 32 rows x 512 k
    const int t7   = tid & 127;
    const int srow = t7 >> 2;            // 0..31
    const int q4   = t7 & 3;             // k128 block within half

    for (int t = 0; t < T_STEPS; t++) {
        const __nv_bfloat16* hin  = g_hbf[(t + 1) & 1];
        __nv_bfloat16*       hout = g_hbf[t & 1];

        // ---- wait for this k-half's 8 producers (monotonic counter) ----
        if (t7 == 0) {
            const unsigned* ctr = &g_grp2[grp][half][0];
            unsigned vv;
            do {
                asm volatile("ld.acquire.gpu.global.u32 %0, [%1];"
                             : "=r"(vv) : "l"(ctr) : "memory");
            } while (vv < 8u * (unsigned)t);
        }
        asm volatile("bar.sync %0, %1;" :: "r"(1 + half), "r"(128) : "memory");

        // ---- bulk load this half: 16 int4/thread, front-batched ----
        const __nv_bfloat16* gsrc =
            hin + (size_t)(m0 + srow) * HID + half * 512 + q4 * 128;
        int4 v[16];
        #pragma unroll
        for (int j = 0; j < 8; j++) {
            v[2 * j]     = __ldcg((const int4*)(gsrc + j * 16));
            v[2 * j + 1] = __ldcg((const int4*)(gsrc + j * 16 + 8));
        }

        // epilogue operands (overlap with loads/MMA)
        const float* eb = g_E + ((size_t)t * BATCH + m0 + mw + qid) * HID
                              + n0 + nw + 2 * c;
        float2 e00 = __ldg((const float2*)eb);
        float2 e01 = __ldg((const float2*)(eb + 8));
        float2 e10 = __ldg((const float2*)(eb + 8 * HID));
        float2 e11 = __ldg((const float2*)(eb + 8 * HID + 8));

        // ---- stage this half's 32 k16-slices ----
        #pragma unroll
        for (int j = 0; j < 8; j++) {
            const int s  = half * 32 + q4 * 8 + j;
            const int sx = s & 3;
            uint2* dp = (uint2*)(As + s * 256 + srow * 8);
            int4 a = v[2 * j], b = v[2 * j + 1];
            dp[0 ^ sx] = make_uint2(a.x, b.x);
            dp[1 ^ sx] = make_uint2(a.y, b.y);
            dp[2 ^ sx] = make_uint2(a.z, b.z);
            dp[3 ^ sx] = make_uint2(a.w, b.w);
        }
        asm volatile("bar.sync %0, %1;" :: "r"(1 + half), "r"(128) : "memory");

        // ---- MMA: warp (nh, kq); 16 k16-slices, 8 MMAs each (R10 body) ----
        float d[2][4][4];
        #pragma unroll
        for (int mg = 0; mg < 2; mg++)
            #pragma unroll
            for (int ng = 0; ng < 4; ng++)
                #pragma unroll
                for (int j = 0; j < 4; j++) d[mg][ng][j] = 0.0f;

        #pragma unroll
        for (int i = 0; i < 16; i++) {
            const int s = kq * 16 + i;
            const unsigned* Ab = As + s * 256 + 2 * (c ^ (s & 3));
            uint2 a0L = *(const uint2*)(Ab + qid * 8);
            uint2 a0H = *(const uint2*)(Ab + (qid + 8) * 8);
            uint2 a1L = *(const uint2*)(Ab + (qid + 16) * 8);
            uint2 a1H = *(const uint2*)(Ab + (qid + 24) * 8);
            const unsigned* Wb = Ws + s * 512 + (nh * 32 + qid) * 8 + 2 * c;
            uint2 b0 = *(const uint2*)(Wb);
            uint2 b1 = *(const uint2*)(Wb + 64);
            uint2 b2 = *(const uint2*)(Wb + 128);
            uint2 b3 = *(const uint2*)(Wb + 192);
            mma_bf16(d[0][0], a0L.x, a0H.x, a0L.y, a0H.y, b0.x, b0.y);
            mma_bf16(d[0][1], a0L.x, a0H.x, a0L.y, a0H.y, b1.x, b1.y);
            mma_bf16(d[0][2], a0L.x, a0H.x, a0L.y, a0H.y, b2.x, b2.y);
            mma_bf16(d[0][3], a0L.x, a0H.x, a0L.y, a0H.y, b3.x, b3.y);
            mma_bf16(d[1][0], a1L.x, a1H.x, a1L.y, a1H.y, b0.x, b0.y);
            mma_bf16(d[1][1], a1L.x, a1H.x, a1L.y, a1H.y, b1.x, b1.y);
            mma_bf16(d[1][2], a1L.x, a1H.x, a1L.y, a1H.y, b2.x, b2.y);
            mma_bf16(d[1][3], a1L.x, a1H.x, a1L.y, a1H.y, b3.x, b3.y);
        }
        // WAR: both warps of this half done reading before Red overlays it
        asm volatile("bar.sync %0, %1;" :: "r"(1 + half), "r"(128) : "memory");

        // ---- write fp32 k-partials into Red (remapped into own half) ----
        float* rq = Red + half * 8192 + (kq & 1) * RKQ;
        #pragma unroll
        for (int mg = 0; mg < 2; mg++) {
            #pragma unroll
            for (int ng = 0; ng < 4; ng++) {
                float* rp = rq + (mg * 16 + qid) * RSTR
                          + nh * 32 + ng * 8 + 2 * c;
                *(float2*)rp              = make_float2(d[mg][ng][0], d[mg][ng][1]);
                *(float2*)(rp + 8 * RSTR) = make_float2(d[mg][ng][2], d[mg][ng][3]);
            }
        }
        __syncthreads();

        // ---- epilogue: reduce 4 k-partials (bases 0, RKQ, 8192, 8192+RKQ)
        const int ml = mw + qid;
        const int nl = nw + 2 * c;
        const float* r0 = Red + ml * RSTR + nl;
        float2 f00, f01, f10, f11;
        {
            float2 p0 = *(const float2*)(r0);
            float2 p1 = *(const float2*)(r0 + RKQ);
            float2 p2 = *(const float2*)(r0 + 8192);
            float2 p3 = *(const float2*)(r0 + 8192 + RKQ);
            f00.x = (p0.x + p1.x) + (p2.x + p3.x);
            f00.y = (p0.y + p1.y) + (p2.y + p3.y);
        }
        {
            const float* r = r0 + 8;
            float2 p0 = *(const float2*)(r);
            float2 p1 = *(const float2*)(r + RKQ);
            float2 p2 = *(const float2*)(r + 8192);
            float2 p3 = *(const float2*)(r + 8192 + RKQ);
            f01.x = (p0.x + p1.x) + (p2.x + p3.x);
            f01.y = (p0.y + p1.y) + (p2.y + p3.y);
        }
        {
            const float* r = r0 + 8 * RSTR;
            float2 p0 = *(const float2*)(r);
            float2 p1 = *(const float2*)(r + RKQ);
            float2 p2 = *(const float2*)(r + 8192);
            float2 p3 = *(const float2*)(r + 8192 + RKQ);
            f10.x = (p0.x + p1.x) + (p2.x + p3.x);
            f10.y = (p0.y + p1.y) + (p2.y + p3.y);
        }
        {
            const float* r = r0 + 8 * RSTR + 8;
            float2 p0 = *(const float2*)(r);
            float2 p1 = *(const float2*)(r + RKQ);
            float2 p2 = *(const float2*)(r + 8192);
            float2 p3 = *(const float2*)(r + 8192 + RKQ);
            f11.x = (p0.x + p1.x) + (p2.x + p3.x);
            f11.y = (p0.y + p1.y) + (p2.y + p3.y);
        }

        float s00x = sigmoidf_fast(f00.x + bh0.x + e00.x);
        float s00y = sigmoidf_fast(f00.y + bh0.y + e00.y);
        float s10x = sigmoidf_fast(f10.x + bh0.x + e10.x);
        float s10y = sigmoidf_fast(f10.y + bh0.y + e10.y);
        float s01x = sigmoidf_fast(f01.x + bh1.x + e01.x);
        float s01y = sigmoidf_fast(f01.y + bh1.y + e01.y);
        float s11x = sigmoidf_fast(f11.x + bh1.x + e11.x);
        float s11y = sigmoidf_fast(f11.y + bh1.y + e11.y);

        __nv_bfloat16* ho = hout + (size_t)(m0 + ml) * HID + n0 + nl;
        *(__nv_bfloat162*)(ho)               = __float22bfloat162_rn(make_float2(s00x, s00y));
        *(__nv_bfloat162*)(ho + 8)           = __float22bfloat162_rn(make_float2(s01x, s01y));
        *(__nv_bfloat162*)(ho + 8 * HID)     = __float22bfloat162_rn(make_float2(s10x, s10y));
        *(__nv_bfloat162*)(ho + 8 * HID + 8) = __float22bfloat162_rn(make_float2(s11x, s11y));

        if (t == T_STEPS - 1) {
            float* hf = g_hfinal + (size_t)(m0 + ml) * HID + n0 + nl;
            *(float2*)(hf)               = make_float2(s00x, s00y);
            *(float2*)(hf + 8)           = make_float2(s01x, s01y);
            *(float2*)(hf + 8 * HID)     = make_float2(s10x, s10y);
            *(float2*)(hf + 8 * HID + 8) = make_float2(s11x, s11y);
        } else {
            // publish: all h stores done, then one release into this
            // producer's k-half counter (myp<8 -> half 0, else half 1)
            __syncthreads();
            if (tid == 0) {
                asm volatile("red.release.gpu.global.add.u32 [%0], %1;"
                             :: "l"(&g_grp2[grp][myp >> 3][0]), "r"(1u)
                             : "memory");
            }
        }
    }
}

// ---------------------------------------------------------------------------
// Final head (all 128 threads participate in the dot product)
// ---------------------------------------------------------------------------
__global__ void finalize_kernel(const float* __restrict__ h,
                                const float* __restrict__ state_in,
                                const float* __restrict__ W_o,
                                const float* __restrict__ b_o,
                                float* __restrict__ out)
{
    const int b    = blockIdx.x;
    const int tid  = threadIdx.x;
    const int lane = tid & 31;
    const int wid  = tid >> 5;

    __shared__ float red[4][OUTD];
    __shared__ float logits[OUTD];

    float acc[OUTD];
    #pragma unroll
    for (int o = 0; o < OUTD; o++) acc[o] = 0.0f;
    for (int k = tid; k < HID; k += 128) {
        float hv = h[(size_t)b * HID + k];
        #pragma unroll
        for (int o = 0; o < OUTD; o++)
            acc[o] += hv * W_o[(size_t)o * HID + k];
    }
    #pragma unroll
    for (int o = 0; o < OUTD; o++) {
        float v = acc[o];
        #pragma unroll
        for (int s = 16; s > 0; s >>= 1)
            v += __shfl_xor_sync(0xffffffff, v, s);
        if (lane == 0) red[wid][o] = v;
    }
    __syncthreads();

    if (tid == 0) {
        #pragma unroll
        for (int o = 0; o < OUTD; o++)
            logits[o] = red[0][o] + red[1][o] + red[2][o] + red[3][o] + b_o[o];
        float m = logits[0];
        #pragma unroll
        for (int o = 1; o < OUTD; o++) m = fmaxf(m, logits[o]);
        float s = 0.0f;
        #pragma unroll
        for (int o = 0; o < OUTD; o++) s += expf(logits[o] - m);
        float lse = m + logf(s);
        #pragma unroll
        for (int o = 0; o < OUTD; o++)
            out[(size_t)b * OUTD + o] = logits[o] - lse;
    }

    float* hid_out = out + (size_t)BATCH * OUTD;
    float* st_out  = hid_out + (size_t)BATCH * HID;
    for (int k = tid; k < HID; k += blockDim.x) {
        hid_out[(size_t)b * HID + k] = h[(size_t)b * HID + k];
        st_out[(size_t)b * HID + k]  = state_in[(size_t)b * HID + k];
    }
}

extern "C" void kernel_launch(void* const* d_in, const int* in_sizes, int n_in,
                              void* d_out, int out_size)
{
    const float* x    = (const float*)d_in[0];
    const float* h0   = (const float*)d_in[1];
    const float* st   = (const float*)d_in[2];
    const float* W_in = (const float*)d_in[3];
    const float* b_in = (const float*)d_in[4];
    const float* W_h  = (const float*)d_in[5];
    const float* b_h  = (const float*)d_in[6];
    const float* W_o  = (const float*)d_in[7];
    const float* b_o  = (const float*)d_in[8];
    float* out = (float*)d_out;

    float* Eptr = nullptr;
    float* hfin = nullptr;
    unsigned* grpptr = nullptr;
    cudaGetSymbolAddress((void**)&Eptr, g_E);
    cudaGetSymbolAddress((void**)&hfin, g_hfinal);
    cudaGetSymbolAddress((void**)&grpptr, g_grp2);

    // reset k-half barrier counters (graph replays must see zeros)
    cudaMemsetAsync(grpptr, 0, 8 * 2 * 32 * sizeof(unsigned));

    // 0) h0 -> bf16 transport buffer
    h0_to_bf16<<<(BATCH * HID) / 256, 256>>>(h0);

    // 1) E = x @ W_in^T + b_in (single-pass bf16, fp32 accumulate)
    {
        const int smem_bytes = 12288 * sizeof(unsigned);  // 48KB
        cudaFuncSetAttribute(egemm_bf16,
                             cudaFuncAttributeMaxDynamicSharedMemorySize, smem_bytes);
        dim3 grid(HID / 64, (T_STEPS * BATCH) / 128);
        egemm_bf16<<<grid, 256, smem_bytes>>>(x, W_in, b_in, Eptr);
    }

    // 1.5) shift ncu's capture slot onto rnn_persistent
    ncu_shift_dummy<<<1, 32>>>();

    // 2) Persistent recurrence (R15: split k-half barriers, warp-quad halves)
    {
        const int smem_bytes = (32768 + 16384) * sizeof(unsigned);  // 192KB
        cudaFuncSetAttribute(rnn_persistent,
                             cudaFuncAttributeMaxDynamicSharedMemorySize, smem_bytes);
        rnn_persistent<<<GRID_P, 256, smem_bytes>>>(W_h, b_h);
    }

    // 3) Head + output tuple
    finalize_kernel<<<BATCH, 128>>>(hfin, st, W_o, b_o, out);
}

// round 17
// speedup vs baseline: 1.2085x; 1.2085x over previous
#include <cuda_runtime.h>
#include <cuda_bf16.h>
#include <math.h>

// Problem dims (fixed by the reference)
#define T_STEPS 512
#define BATCH   256
#define DIM     1024
#define HID     1024
#define OUTD    5

// Recurrence (R10 shell): 128 CTAs = 8 m-groups(32) x 16 n-tiles(64)
#define GRID_P  128
#define MT      32
#define NT      64
#define RSTR    68            // padded fp32 row stride in reduction buffer
#define RKQ     (32 * RSTR)   // per-k-quarter stride (2176 words)

// Scratch
__device__ float          g_E[(size_t)T_STEPS * BATCH * HID];     // fp32 input proj
__device__ __nv_bfloat16  g_hbf[2][(size_t)BATCH * HID];          // bf16 h transport
__device__ float          g_hfinal[(size_t)BATCH * HID];          // fp32 final h
__device__ unsigned       g_grp[8][32];                           // per-m-group barrier ctrs

// ---------------------------------------------------------------------------
__device__ __forceinline__ void mma_bf16(float d[4],
                                         unsigned a0, unsigned a1,
                                         unsigned a2, unsigned a3,
                                         unsigned b0, unsigned b1)
{
    asm volatile(
        "mma.sync.aligned.m16n8k16.row.col.f32.bf16.bf16.f32 "
        "{%0,%1,%2,%3}, {%4,%5,%6,%7}, {%8,%9}, {%0,%1,%2,%3};"
        : "+f"(d[0]), "+f"(d[1]), "+f"(d[2]), "+f"(d[3])
        : "r"(a0), "r"(a1), "r"(a2), "r"(a3), "r"(b0), "r"(b1));
}

__device__ __forceinline__ float sigmoidf_fast(float x)
{
    return 1.0f / (1.0f + __expf(-x));
}

// ---------------------------------------------------------------------------
// E = x @ W_in^T + b_in, single-pass bf16 tensor-core GEMM (validated R7/R8).
// ---------------------------------------------------------------------------
__global__ void __launch_bounds__(256, 2)
egemm_bf16(const float* __restrict__ X,     // [131072, 1024]
           const float* __restrict__ Wg,    // [1024, 1024]
           const float* __restrict__ bias,  // [1024]
           float* __restrict__ E)
{
    extern __shared__ unsigned es[];
    unsigned* Ah = es;              // 8192 words (32KB)
    unsigned* Bh = es + 8192;       // 4096 words (16KB)

    const int tid  = threadIdx.x;
    const int lane = tid & 31;
    const int w    = tid >> 5;
    const int qid  = lane >> 2;
    const int c    = lane & 3;
    const int g    = w >> 1;
    const int subm = (w & 1) * 16;

    const int n0 = blockIdx.x * 64;
    const int m0 = blockIdx.y * 128;

    const int srow = tid >> 3;
    const int ssl  = tid & 7;
    const int sx   = ssl & 3;

    float acc[4][2][4];
    #pragma unroll
    for (int a = 0; a < 4; a++)
        #pragma unroll
        for (int b = 0; b < 2; b++)
            #pragma unroll
            for (int d = 0; d < 4; d++) acc[a][b][d] = 0.0f;

    for (int ch = 0; ch < 8; ch++) {
        __syncthreads();
        const float* xbase = X + (size_t)(m0 + srow) * 1024 + ch * 128 + ssl * 16;
        #pragma unroll
        for (int jj = 0; jj < 4; jj++) {
            const float4* p = (const float4*)(xbase + (size_t)jj * 32 * 1024);
            float4 f0 = p[0], f1 = p[1], f2 = p[2], f3 = p[3];
            unsigned h[8];
            {
                __nv_bfloat162 b0 = __float22bfloat162_rn(make_float2(f0.x, f0.y));
                __nv_bfloat162 b1 = __float22bfloat162_rn(make_float2(f0.z, f0.w));
                __nv_bfloat162 b2 = __float22bfloat162_rn(make_float2(f1.x, f1.y));
                __nv_bfloat162 b3 = __float22bfloat162_rn(make_float2(f1.z, f1.w));
                __nv_bfloat162 b4 = __float22bfloat162_rn(make_float2(f2.x, f2.y));
                __nv_bfloat162 b5 = __float22bfloat162_rn(make_float2(f2.z, f2.w));
                __nv_bfloat162 b6 = __float22bfloat162_rn(make_float2(f3.x, f3.y));
                __nv_bfloat162 b7 = __float22bfloat162_rn(make_float2(f3.z, f3.w));
                h[0] = *(unsigned*)&b0; h[1] = *(unsigned*)&b1;
                h[2] = *(unsigned*)&b2; h[3] = *(unsigned*)&b3;
                h[4] = *(unsigned*)&b4; h[5] = *(unsigned*)&b5;
                h[6] = *(unsigned*)&b6; h[7] = *(unsigned*)&b7;
            }
            uint2* dh = (uint2*)&Ah[jj * 2048 + ssl * 256 + srow * 8];
            dh[0 ^ sx] = make_uint2(h[0], h[4]);
            dh[1 ^ sx] = make_uint2(h[1], h[5]);
            dh[2 ^ sx] = make_uint2(h[2], h[6]);
            dh[3 ^ sx] = make_uint2(h[3], h[7]);
        }
        #pragma unroll
        for (int jj = 0; jj < 2; jj++) {
            int nrow = srow + jj * 32;
            const float4* p = (const float4*)(Wg + (size_t)(n0 + nrow) * 1024
                                              + ch * 128 + ssl * 16);
            float4 f0 = p[0], f1 = p[1], f2 = p[2], f3 = p[3];
            unsigned h[8];
            {
                __nv_bfloat162 b0 = __float22bfloat162_rn(make_float2(f0.x, f0.y));
                __nv_bfloat162 b1 = __float22bfloat162_rn(make_float2(f0.z, f0.w));
                __nv_bfloat162 b2 = __float22bfloat162_rn(make_float2(f1.x, f1.y));
                __nv_bfloat162 b3 = __float22bfloat162_rn(make_float2(f1.z, f1.w));
                __nv_bfloat162 b4 = __float22bfloat162_rn(make_float2(f2.x, f2.y));
                __nv_bfloat162 b5 = __float22bfloat162_rn(make_float2(f2.z, f2.w));
                __nv_bfloat162 b6 = __float22bfloat162_rn(make_float2(f3.x, f3.y));
                __nv_bfloat162 b7 = __float22bfloat162_rn(make_float2(f3.z, f3.w));
                h[0] = *(unsigned*)&b0; h[1] = *(unsigned*)&b1;
                h[2] = *(unsigned*)&b2; h[3] = *(unsigned*)&b3;
                h[4] = *(unsigned*)&b4; h[5] = *(unsigned*)&b5;
                h[6] = *(unsigned*)&b6; h[7] = *(unsigned*)&b7;
            }
            uint2* dh = (uint2*)&Bh[ssl * 512 + nrow * 8];
            dh[0 ^ sx] = make_uint2(h[0], h[4]);
            dh[1 ^ sx] = make_uint2(h[1], h[5]);
            dh[2 ^ sx] = make_uint2(h[2], h[6]);
            dh[3 ^ sx] = make_uint2(h[3], h[7]);
        }
        __syncthreads();

        #pragma unroll
        for (int sl = 0; sl < 8; sl++) {
            int axw = g * 2048 + sl * 256 + (subm + qid) * 8 + 2 * (c ^ (sl & 3));
            uint2 ah0 = *(const uint2*)&Ah[axw];
            uint2 ah1 = *(const uint2*)&Ah[axw + 64];
            #pragma unroll
            for (int ng = 0; ng < 4; ng++) {
                int bxw = sl * 512 + ng * 128 + qid * 8 + 2 * (c ^ (sl & 3));
                uint2 bh0 = *(const uint2*)&Bh[bxw];
                uint2 bh1 = *(const uint2*)&Bh[bxw + 64];
                mma_bf16(acc[ng][0], ah0.x, ah1.x, ah0.y, ah1.y, bh0.x, bh0.y);
                mma_bf16(acc[ng][1], ah0.x, ah1.x, ah0.y, ah1.y, bh1.x, bh1.y);
            }
        }
    }

    const int mrow = m0 + w * 16 + qid;
    #pragma unroll
    for (int ng = 0; ng < 4; ng++) {
        #pragma unroll
        for (int hh = 0; hh < 2; hh++) {
            int col = n0 + ng * 16 + hh * 8 + 2 * c;
            float2 b2 = *(const float2*)(bias + col);
            float2 o0, o1;
            o0.x = acc[ng][hh][0] + b2.x; o0.y = acc[ng][hh][1] + b2.y;
            o1.x = acc[ng][hh][2] + b2.x; o1.y = acc[ng][hh][3] + b2.y;
            *(float2*)&E[(size_t)mrow * 1024 + col]       = o0;
            *(float2*)&E[(size_t)(mrow + 8) * 1024 + col] = o1;
        }
    }
}

// ---------------------------------------------------------------------------
__global__ void h0_to_bf16(const float* __restrict__ h0)
{
    int i = blockIdx.x * 256 + threadIdx.x;
    g_hbf[1][i] = __float2bfloat16(h0[i]);
}

// Dummy launch: shifts ncu's fixed capture slot onto rnn_persistent.
__global__ void ncu_shift_dummy() {}

// ---------------------------------------------------------------------------
// Per-m-group barrier: 16 CTAs, release/acquire atomics, monotonic counter.
// ---------------------------------------------------------------------------
__device__ __forceinline__ void group_barrier(int grp, unsigned target)
{
    __syncthreads();
    if (threadIdx.x == 0) {
        unsigned* ctr = &g_grp[grp][0];
        asm volatile("red.release.gpu.global.add.u32 [%0], %1;"
                     :: "l"(ctr), "r"(1u) : "memory");
        unsigned v;
        do {
            asm volatile("ld.acquire.gpu.global.u32 %0, [%1];"
                         : "=r"(v) : "l"(ctr) : "memory");
        } while (v < target);
    }
    __syncthreads();
}

// ---------------------------------------------------------------------------
// Persistent recurrence — R10 structure (5123us verified best): 128 CTAs,
// 32m x 64n, Ws-resident W_h, bulk MLP=16 h load, one stage sync, split-K
// warps (nh = w&1, kq = w>>1), Red reduction, monolithic group barrier.
// ---------------------------------------------------------------------------
__global__ void __launch_bounds__(256, 1)
rnn_persistent(const float* __restrict__ W_h,
               const float* __restrict__ b_h)
{
    extern __shared__ unsigned smw[];
    unsigned* Ws = smw;              // 32768 words (128KB)
    unsigned* As = smw + 32768;      // 16384 words (64KB)
    float*    Red = (float*)As;      // reduction buffer (reuses As)

    const int tid  = threadIdx.x;
    const int lane = tid & 31;
    const int w    = tid >> 5;
    const int qid  = lane >> 2;
    const int c    = lane & 3;
    const int mw   = (w >> 2) * 16;  // epilogue coords (R10 mapping)
    const int nw   = (w & 3) * 16;
    const int nh   = w & 1;          // MMA role: n-half (32 cols)
    const int kq   = w >> 1;         // MMA role: k-quarter (256 k)
    const int cta  = blockIdx.x;
    const int grp  = cta >> 4;
    const int m0   = grp * MT;
    const int n0   = (cta & 15) * NT;

    // ---- fill Ws (once): fp32 -> bf16x2, fragment-shuffled (R8 layout) ----
    for (int i = tid; i < NT * 512; i += 256) {
        int n  = i >> 9;
        int kp = i & 511;
        int k  = kp * 2;
        int s  = k >> 4;
        int p  = (k & 15) >> 1;
        float2 wv = *(const float2*)(W_h + (size_t)(n0 + n) * HID + k);
        __nv_bfloat162 bb = __float22bfloat162_rn(wv);
        Ws[s * 512 + n * 8 + (p & 3) * 2 + (p >> 2)] = *(unsigned*)&bb;
    }
    const float2 bh0 = *(const float2*)(b_h + n0 + nw + 2 * c);
    const float2 bh1 = *(const float2*)(b_h + n0 + nw + 8 + 2 * c);
    __syncthreads();

    const int srow = tid >> 3;
    const int ssl  = tid & 7;
    const int sx   = ssl & 3;

    for (int t = 0; t < T_STEPS; t++) {
        const __nv_bfloat16* hin  = g_hbf[(t + 1) & 1];
        __nv_bfloat16*       hout = g_hbf[t & 1];

        // ---- bulk load: whole h tile, 16 int4 per thread, front-batched ----
        const __nv_bfloat16* gsrc = hin + (size_t)(m0 + srow) * HID + ssl * 16;
        int4 v[16];
        #pragma unroll
        for (int ch = 0; ch < 8; ch++) {
            v[2 * ch]     = __ldcg((const int4*)(gsrc + ch * 128));
            v[2 * ch + 1] = __ldcg((const int4*)(gsrc + ch * 128 + 8));
        }

        // epilogue operands (overlap with h loads)
        const float* eb = g_E + ((size_t)t * BATCH + m0 + mw + qid) * HID
                              + n0 + nw + 2 * c;
        float2 e00 = __ldg((const float2*)eb);
        float2 e01 = __ldg((const float2*)(eb + 8));
        float2 e10 = __ldg((const float2*)(eb + 8 * HID));
        float2 e11 = __ldg((const float2*)(eb + 8 * HID + 8));

        // ---- stage all 8 chunks, one sync ----
        #pragma unroll
        for (int ch = 0; ch < 8; ch++) {
            uint2* dp = (uint2*)(As + ch * 2048 + ssl * 256 + srow * 8);
            int4 a = v[2 * ch], b = v[2 * ch + 1];
            dp[0 ^ sx] = make_uint2(a.x, b.x);
            dp[1 ^ sx] = make_uint2(a.y, b.y);
            dp[2 ^ sx] = make_uint2(a.z, b.z);
            dp[3 ^ sx] = make_uint2(a.w, b.w);
        }
        __syncthreads();

        // ---- MMA phase: warp = (nh, kq); 16 k16-slices, 8 MMAs each ----
        float d[2][4][4];
        #pragma unroll
        for (int mg = 0; mg < 2; mg++)
            #pragma unroll
            for (int ng = 0; ng < 4; ng++)
                #pragma unroll
                for (int j = 0; j < 4; j++) d[mg][ng][j] = 0.0f;

        #pragma unroll
        for (int i = 0; i < 16; i++) {
            const int s = kq * 16 + i;
            const unsigned* Ab = As + s * 256 + 2 * (c ^ (s & 3));
            uint2 a0L = *(const uint2*)(Ab + qid * 8);           // rows qid
            uint2 a0H = *(const uint2*)(Ab + (qid + 8) * 8);     // rows qid+8
            uint2 a1L = *(const uint2*)(Ab + (qid + 16) * 8);    // rows qid+16
            uint2 a1H = *(const uint2*)(Ab + (qid + 24) * 8);    // rows qid+24
            const unsigned* Wb = Ws + s * 512 + (nh * 32 + qid) * 8 + 2 * c;
            uint2 b0 = *(const uint2*)(Wb);                      // n8 group 0
            uint2 b1 = *(const uint2*)(Wb + 64);                 // +8
            uint2 b2 = *(const uint2*)(Wb + 128);                // +16
            uint2 b3 = *(const uint2*)(Wb + 192);                // +24
            mma_bf16(d[0][0], a0L.x, a0H.x, a0L.y, a0H.y, b0.x, b0.y);
            mma_bf16(d[0][1], a0L.x, a0H.x, a0L.y, a0H.y, b1.x, b1.y);
            mma_bf16(d[0][2], a0L.x, a0H.x, a0L.y, a0H.y, b2.x, b2.y);
            mma_bf16(d[0][3], a0L.x, a0H.x, a0L.y, a0H.y, b3.x, b3.y);
            mma_bf16(d[1][0], a1L.x, a1H.x, a1L.y, a1H.y, b0.x, b0.y);
            mma_bf16(d[1][1], a1L.x, a1H.x, a1L.y, a1H.y, b1.x, b1.y);
            mma_bf16(d[1][2], a1L.x, a1H.x, a1L.y, a1H.y, b2.x, b2.y);
            mma_bf16(d[1][3], a1L.x, a1H.x, a1L.y, a1H.y, b3.x, b3.y);
        }
        __syncthreads();   // all As (h tile) reads complete

        // ---- write fp32 k-partials into Red (reuses As) ----
        #pragma unroll
        for (int mg = 0; mg < 2; mg++) {
            #pragma unroll
            for (int ng = 0; ng < 4; ng++) {
                float* rp = Red + kq * RKQ + (mg * 16 + qid) * RSTR
                          + nh * 32 + ng * 8 + 2 * c;
                *(float2*)rp             = make_float2(d[mg][ng][0], d[mg][ng][1]);
                *(float2*)(rp + 8 * RSTR) = make_float2(d[mg][ng][2], d[mg][ng][3]);
            }
        }
        __syncthreads();

        // ---- epilogue: reduce 4 k-partials, + b_h + E, sigmoid ----
        const int ml = mw + qid;
        const int nl = nw + 2 * c;
        const float* r0 = Red + ml * RSTR + nl;
        float2 f00, f01, f10, f11;
        {
            float2 p0 = *(const float2*)(r0);
            float2 p1 = *(const float2*)(r0 + RKQ);
            float2 p2 = *(const float2*)(r0 + 2 * RKQ);
            float2 p3 = *(const float2*)(r0 + 3 * RKQ);
            f00.x = (p0.x + p1.x) + (p2.x + p3.x);
            f00.y = (p0.y + p1.y) + (p2.y + p3.y);
        }
        {
            const float* r = r0 + 8;
            float2 p0 = *(const float2*)(r);
            float2 p1 = *(const float2*)(r + RKQ);
            float2 p2 = *(const float2*)(r + 2 * RKQ);
            float2 p3 = *(const float2*)(r + 3 * RKQ);
            f01.x = (p0.x + p1.x) + (p2.x + p3.x);
            f01.y = (p0.y + p1.y) + (p2.y + p3.y);
        }
        {
            const float* r = r0 + 8 * RSTR;
            float2 p0 = *(const float2*)(r);
            float2 p1 = *(const float2*)(r + RKQ);
            float2 p2 = *(const float2*)(r + 2 * RKQ);
            float2 p3 = *(const float2*)(r + 3 * RKQ);
            f10.x = (p0.x + p1.x) + (p2.x + p3.x);
            f10.y = (p0.y + p1.y) + (p2.y + p3.y);
        }
        {
            const float* r = r0 + 8 * RSTR + 8;
            float2 p0 = *(const float2*)(r);
            float2 p1 = *(const float2*)(r + RKQ);
            float2 p2 = *(const float2*)(r + 2 * RKQ);
            float2 p3 = *(const float2*)(r + 3 * RKQ);
            f11.x = (p0.x + p1.x) + (p2.x + p3.x);
            f11.y = (p0.y + p1.y) + (p2.y + p3.y);
        }

        float s00x = sigmoidf_fast(f00.x + bh0.x + e00.x);
        float s00y = sigmoidf_fast(f00.y + bh0.y + e00.y);
        float s10x = sigmoidf_fast(f10.x + bh0.x + e10.x);
        float s10y = sigmoidf_fast(f10.y + bh0.y + e10.y);
        float s01x = sigmoidf_fast(f01.x + bh1.x + e01.x);
        float s01y = sigmoidf_fast(f01.y + bh1.y + e01.y);
        float s11x = sigmoidf_fast(f11.x + bh1.x + e11.x);
        float s11y = sigmoidf_fast(f11.y + bh1.y + e11.y);

        __nv_bfloat16* ho = hout + (size_t)(m0 + ml) * HID + n0 + nl;
        *(__nv_bfloat162*)(ho)               = __float22bfloat162_rn(make_float2(s00x, s00y));
        *(__nv_bfloat162*)(ho + 8)           = __float22bfloat162_rn(make_float2(s01x, s01y));
        *(__nv_bfloat162*)(ho + 8 * HID)     = __float22bfloat162_rn(make_float2(s10x, s10y));
        *(__nv_bfloat162*)(ho + 8 * HID + 8) = __float22bfloat162_rn(make_float2(s11x, s11y));

        if (t == T_STEPS - 1) {
            float* hf = g_hfinal + (size_t)(m0 + ml) * HID + n0 + nl;
            *(float2*)(hf)               = make_float2(s00x, s00y);
            *(float2*)(hf + 8)           = make_float2(s01x, s01y);
            *(float2*)(hf + 8 * HID)     = make_float2(s10x, s10y);
            *(float2*)(hf + 8 * HID + 8) = make_float2(s11x, s11y);
        } else {
            group_barrier(grp, 16u * (t + 1));
        }
    }
}

// ---------------------------------------------------------------------------
// Final head (all 128 threads participate in the dot product)
// ---------------------------------------------------------------------------
__global__ void finalize_kernel(const float* __restrict__ h,
                                const float* __restrict__ state_in,
                                const float* __restrict__ W_o,
                                const float* __restrict__ b_o,
                                float* __restrict__ out)
{
    const int b    = blockIdx.x;
    const int tid  = threadIdx.x;
    const int lane = tid & 31;
    const int wid  = tid >> 5;

    __shared__ float red[4][OUTD];
    __shared__ float logits[OUTD];

    float acc[OUTD];
    #pragma unroll
    for (int o = 0; o < OUTD; o++) acc[o] = 0.0f;
    for (int k = tid; k < HID; k += 128) {
        float hv = h[(size_t)b * HID + k];
        #pragma unroll
        for (int o = 0; o < OUTD; o++)
            acc[o] += hv * W_o[(size_t)o * HID + k];
    }
    #pragma unroll
    for (int o = 0; o < OUTD; o++) {
        float v = acc[o];
        #pragma unroll
        for (int s = 16; s > 0; s >>= 1)
            v += __shfl_xor_sync(0xffffffff, v, s);
        if (lane == 0) red[wid][o] = v;
    }
    __syncthreads();

    if (tid == 0) {
        #pragma unroll
        for (int o = 0; o < OUTD; o++)
            logits[o] = red[0][o] + red[1][o] + red[2][o] + red[3][o] + b_o[o];
        float m = logits[0];
        #pragma unroll
        for (int o = 1; o < OUTD; o++) m = fmaxf(m, logits[o]);
        float s = 0.0f;
        #pragma unroll
        for (int o = 0; o < OUTD; o++) s += expf(logits[o] - m);
        float lse = m + logf(s);
        #pragma unroll
        for (int o = 0; o < OUTD; o++)
            out[(size_t)b * OUTD + o] = logits[o] - lse;
    }

    float* hid_out = out + (size_t)BATCH * OUTD;
    float* st_out  = hid_out + (size_t)BATCH * HID;
    for (int k = tid; k < HID; k += blockDim.x) {
        hid_out[(size_t)b * HID + k] = h[(size_t)b * HID + k];
        st_out[(size_t)b * HID + k]  = state_in[(size_t)b * HID + k];
    }
}

extern "C" void kernel_launch(void* const* d_in, const int* in_sizes, int n_in,
                              void* d_out, int out_size)
{
    const float* x    = (const float*)d_in[0];
    const float* h0   = (const float*)d_in[1];
    const float* st   = (const float*)d_in[2];
    const float* W_in = (const float*)d_in[3];
    const float* b_in = (const float*)d_in[4];
    const float* W_h  = (const float*)d_in[5];
    const float* b_h  = (const float*)d_in[6];
    const float* W_o  = (const float*)d_in[7];
    const float* b_o  = (const float*)d_in[8];
    float* out = (float*)d_out;

    float* Eptr = nullptr;
    float* hfin = nullptr;
    unsigned* grpptr = nullptr;
    cudaGetSymbolAddress((void**)&Eptr, g_E);
    cudaGetSymbolAddress((void**)&hfin, g_hfinal);
    cudaGetSymbolAddress((void**)&grpptr, g_grp);

    cudaMemsetAsync(grpptr, 0, 8 * 32 * sizeof(unsigned));

    // 0) h0 -> bf16 transport buffer
    h0_to_bf16<<<(BATCH * HID) / 256, 256>>>(h0);

    // 1) E = x @ W_in^T + b_in (single-pass bf16, fp32 accumulate)
    {
        const int smem_bytes = 12288 * sizeof(unsigned);  // 48KB
        cudaFuncSetAttribute(egemm_bf16,
                             cudaFuncAttributeMaxDynamicSharedMemorySize, smem_bytes);
        dim3 grid(HID / 64, (T_STEPS * BATCH) / 128);
        egemm_bf16<<<grid, 256, smem_bytes>>>(x, W_in, b_in, Eptr);
    }

    // 1.5) shift ncu's capture slot onto rnn_persistent
    ncu_shift_dummy<<<1, 32>>>();

    // 2) Persistent recurrence (R10: split-K warps, verified 5123us best)
    {
        const int smem_bytes = (32768 + 16384) * sizeof(unsigned);  // 192KB
        cudaFuncSetAttribute(rnn_persistent,
                             cudaFuncAttributeMaxDynamicSharedMemorySize, smem_bytes);
        rnn_persistent<<<GRID_P, 256, smem_bytes>>>(W_h, b_h);
    }

    // 3) Head + output tuple
    finalize_kernel<<<BATCH, 128>>>(hfin, st, W_o, b_o, out);
}